// round 1
// baseline (speedup 1.0000x reference)
#include <cuda_runtime.h>

#define NVV 50000
#define NCC 50000
#define DD 128
#define FIN 32
#define DEG 16
#define INDIM 288

#define BM 128
#define ASTR 292   // 288 + 4 pad: conflict-free column reads, 16B-aligned rows
#define BSTR 129
#define LAYER_SMEM ((BM*ASTR + 32*BSTR)*4)

// Ping-pong activation buffers: 0/1 = lv, 2/3 = lc
__device__ __align__(256) float g_bufs[4][(size_t)NVV * DD];
__device__ float g_colsum[DD];
__device__ int g_is64;

// ---------------------------------------------------------------------------
// Detect whether index arrays are int64 (high words all zero) or int32.
// ---------------------------------------------------------------------------
__global__ void detect_kernel(const int* __restrict__ idx32) {
    if (threadIdx.x == 0) {
        int nz = 0;
#pragma unroll
        for (int i = 0; i < 64; i++) nz |= idx32[2 * i + 1];
        g_is64 = (nz == 0) ? 1 : 0;
    }
}

__global__ void zero_colsum() {
    if (threadIdx.x < DD) g_colsum[threadIdx.x] = 0.f;
}

// ---------------------------------------------------------------------------
// Initial embedding: out[i][o] = b[o] + sum_{k<32} feat[i][k] * W[o][k]
// 64 rows/block, 256 threads. Each thread owns one output column for 32 rows,
// W row cached in registers, feat tile in smem (broadcast reads).
// ---------------------------------------------------------------------------
__global__ void init_embed(const float* __restrict__ feat,
                           const float* __restrict__ W,
                           const float* __restrict__ b,
                           int out_sel, int n) {
    __shared__ float sF[64][FIN];
    float* out = g_bufs[out_sel];
    int row0 = blockIdx.x * 64;
    int tid = threadIdx.x;

    for (int i = tid; i < 64 * FIN; i += 256) {
        int r = i >> 5, k = i & 31;
        int gr = row0 + r;
        sF[r][k] = (gr < n) ? feat[(size_t)gr * FIN + k] : 0.f;
    }
    __syncthreads();

    int col = tid & 127;
    int rh = tid >> 7;  // 0 or 1
    float w[FIN];
#pragma unroll
    for (int k = 0; k < FIN; k++) w[k] = W[col * FIN + k];
    float bias = b[col];

    int rbeg = rh * 32;
    int rend = rbeg + 32;
    if (row0 + rend > n) rend = (n > row0) ? (n - row0) : 0;
    for (int r = rbeg; r < rend; r++) {
        float acc = bias;
#pragma unroll
        for (int k = 0; k < FIN; k++) acc = fmaf(sF[r][k], w[k], acc);
        out[(size_t)(row0 + r) * DD + col] = acc;
    }
}

// ---------------------------------------------------------------------------
// Fused layer: out[i] = b + W * concat( sum_j aggsrc[idx[i,j]], self[i], feat[i] )
// Phase 1: build 128x288 A-tile in smem (warp-per-row float4 gather-sum).
// Phase 2: 16x16 threads, 8x8 register tiles, W staged in 32-wide K chunks.
// Conflict-free: A reads broadcast per ty (ASTR%32==4), B reads stride-16,
// B stores spread by BSTR=129.
// ---------------------------------------------------------------------------
__global__ __launch_bounds__(256, 1)
void layer_kernel(int agg_sel, int self_sel, int out_sel,
                  const float* __restrict__ feat,
                  const int* __restrict__ idx32,
                  const float* __restrict__ W,
                  const float* __restrict__ b,
                  int n) {
    extern __shared__ float sm[];
    float* As = sm;                 // [BM][ASTR]
    float* Bs = sm + BM * ASTR;     // [32][BSTR]

    const float* aggsrc = g_bufs[agg_sel];
    const float* selfp  = g_bufs[self_sel];
    float* out = g_bufs[out_sel];

    int row0 = blockIdx.x * BM;
    int tid = threadIdx.x;
    int warp = tid >> 5, lane = tid & 31;
    int istride = g_is64 ? 2 : 1;

    // ---- Phase 1: fill A tile ----
    for (int r = warp; r < BM; r += 8) {
        int gr = row0 + r;
        float* arow = As + r * ASTR;
        if (gr < n) {
            const int* ip = idx32 + (size_t)gr * DEG * istride;
            float4 acc = make_float4(0.f, 0.f, 0.f, 0.f);
#pragma unroll
            for (int j = 0; j < DEG; j++) {
                int src = ip[j * istride];
                float4 v = reinterpret_cast<const float4*>(aggsrc + (size_t)src * DD)[lane];
                acc.x += v.x; acc.y += v.y; acc.z += v.z; acc.w += v.w;
            }
            arow[lane*4+0] = acc.x; arow[lane*4+1] = acc.y;
            arow[lane*4+2] = acc.z; arow[lane*4+3] = acc.w;

            float4 sv = reinterpret_cast<const float4*>(selfp + (size_t)gr * DD)[lane];
            arow[128 + lane*4+0] = sv.x; arow[128 + lane*4+1] = sv.y;
            arow[128 + lane*4+2] = sv.z; arow[128 + lane*4+3] = sv.w;

            if (lane < 8) {
                float4 fv = reinterpret_cast<const float4*>(feat + (size_t)gr * FIN)[lane];
                arow[256 + lane*4+0] = fv.x; arow[256 + lane*4+1] = fv.y;
                arow[256 + lane*4+2] = fv.z; arow[256 + lane*4+3] = fv.w;
            }
        } else {
            for (int k = lane; k < INDIM; k += 32) arow[k] = 0.f;
        }
    }
    __syncthreads();

    // ---- Phase 2: GEMM ----
    int tx = tid & 15, ty = tid >> 4;
    float acc[8][8];
#pragma unroll
    for (int r = 0; r < 8; r++)
#pragma unroll
        for (int c = 0; c < 8; c++) acc[r][c] = 0.f;

    for (int kc = 0; kc < INDIM; kc += 32) {
        // stage W chunk, transposed: Bs[k][col] = W[col][kc+k]
        for (int i = tid; i < 128 * 32; i += 256) {
            int nn = i >> 5, k = i & 31;
            Bs[k * BSTR + nn] = W[nn * INDIM + kc + k];
        }
        __syncthreads();
#pragma unroll
        for (int k = 0; k < 32; k++) {
            float a[8], bb[8];
#pragma unroll
            for (int r = 0; r < 8; r++) a[r] = As[(ty + 16*r) * ASTR + kc + k];
#pragma unroll
            for (int c = 0; c < 8; c++) bb[c] = Bs[k * BSTR + tx + 16*c];
#pragma unroll
            for (int r = 0; r < 8; r++)
#pragma unroll
                for (int c = 0; c < 8; c++)
                    acc[r][c] = fmaf(a[r], bb[c], acc[r][c]);
        }
        __syncthreads();
    }

    float bias[8];
#pragma unroll
    for (int c = 0; c < 8; c++) bias[c] = b[tx + 16*c];

#pragma unroll
    for (int r = 0; r < 8; r++) {
        int gr = row0 + ty + 16*r;
        if (gr < n) {
            float* orow = out + (size_t)gr * DD;
#pragma unroll
            for (int c = 0; c < 8; c++)
                orow[tx + 16*c] = acc[r][c] + bias[c];
        }
    }
}

// ---------------------------------------------------------------------------
// Column sum of final lv into g_colsum (atomicAdd per 128-row slab).
// ---------------------------------------------------------------------------
__global__ void colsum_kernel(int lv_sel, int n) {
    const float* lv = g_bufs[lv_sel];
    __shared__ float s[DD];
    int tid = threadIdx.x;
    int col = tid & (DD - 1);
    int half = tid >> 7;
    int r0 = blockIdx.x * 128 + half * 64;
    int r1 = r0 + 64; if (r1 > n) r1 = n;
    float acc = 0.f;
    for (int r = r0; r < r1; r++) acc += lv[(size_t)r * DD + col];
    if (half) s[col] = acc;
    __syncthreads();
    if (!half) atomicAdd(&g_colsum[col], acc + s[col]);
}

// ---------------------------------------------------------------------------
// Q[i] = dot(g_colsum, Wq[0:128]) + b_q + dot(lv[i], Wq[128:256])
// Warp per row, 4 elems/lane, shfl reduce.
// ---------------------------------------------------------------------------
__global__ void final_kernel(int lv_sel, const float* __restrict__ Wq,
                             const float* __restrict__ bq,
                             float* __restrict__ Q, int n) {
    const float* lv = g_bufs[lv_sel];
    __shared__ float sW[DD];
    __shared__ float s_s;
    int tid = threadIdx.x;
    if (tid < DD) sW[tid] = Wq[DD + tid];
    if (tid < 32) {
        float p = 0.f;
#pragma unroll
        for (int t = 0; t < 4; t++) p += g_colsum[tid + 32*t] * Wq[tid + 32*t];
#pragma unroll
        for (int o = 16; o > 0; o >>= 1) p += __shfl_xor_sync(0xffffffffu, p, o);
        if (tid == 0) s_s = p + bq[0];
    }
    __syncthreads();

    int warp = tid >> 5, lane = tid & 31;
    int base = blockIdx.x * 64 + warp * 8;
    for (int i = 0; i < 8; i++) {
        int row = base + i;
        if (row >= n) break;
        const float* rp = lv + (size_t)row * DD;
        float p = rp[lane]        * sW[lane]
                + rp[lane + 32]   * sW[lane + 32]
                + rp[lane + 64]   * sW[lane + 64]
                + rp[lane + 96]   * sW[lane + 96];
#pragma unroll
        for (int o = 16; o > 0; o >>= 1) p += __shfl_xor_sync(0xffffffffu, p, o);
        if (lane == 0) Q[row] = s_s + p;
    }
}

// ---------------------------------------------------------------------------
extern "C" void kernel_launch(void* const* d_in, const int* in_sizes, int n_in,
                              void* d_out, int out_size) {
    const float* x    = (const float*)d_in[0];
    const int*   vci  = (const int*)d_in[1];   // var_constr_index [NV,16]
    const int*   cvi  = (const int*)d_in[2];   // constr_var_index [NC,16]
    const float* W_iv = (const float*)d_in[3];
    const float* b_iv = (const float*)d_in[4];
    const float* W_ic = (const float*)d_in[5];
    const float* b_ic = (const float*)d_in[6];
    const float* W_v  = (const float*)d_in[7];
    const float* b_v  = (const float*)d_in[8];
    const float* W_c  = (const float*)d_in[9];
    const float* b_c  = (const float*)d_in[10];
    const float* W_q  = (const float*)d_in[11];
    const float* b_q  = (const float*)d_in[12];
    float* Q = (float*)d_out;

    cudaFuncSetAttribute(layer_kernel,
                         cudaFuncAttributeMaxDynamicSharedMemorySize, LAYER_SMEM);

    const float* var_feat = x;
    const float* con_feat = x + (size_t)NVV * FIN;

    detect_kernel<<<1, 32>>>(vci);
    init_embed<<<(NVV + 63) / 64, 256>>>(var_feat, W_iv, b_iv, 0, NVV);
    init_embed<<<(NCC + 63) / 64, 256>>>(con_feat, W_ic, b_ic, 2, NCC);

    int lv = 0, lc = 2;
    for (int t = 0; t < 3; t++) {
        int nlc = 5 - lc, nlv = 1 - lv;
        // lc_new = W_c * [gather(lv, constr_var_index), lc, con_feat] + b_c
        layer_kernel<<<(NCC + BM - 1) / BM, 256, LAYER_SMEM>>>(
            lv, lc, nlc, con_feat, cvi, W_c, b_c, NCC);
        // lv_new = W_v * [gather(lc_old, var_constr_index), lv, var_feat] + b_v
        layer_kernel<<<(NVV + BM - 1) / BM, 256, LAYER_SMEM>>>(
            lc, lv, nlv, var_feat, vci, W_v, b_v, NVV);
        lv = nlv; lc = nlc;
    }

    zero_colsum<<<1, 128>>>();
    colsum_kernel<<<(NVV + 127) / 128, 256>>>(lv, NVV);
    final_kernel<<<(NVV + 63) / 64, 256>>>(lv, W_q, b_q, Q, NVV);
}

// round 3
// speedup vs baseline: 1.5113x; 1.5113x over previous
#include <cuda_runtime.h>
#include <cuda_bf16.h>
#include <cstdint>

#define NVV 50000
#define DD 128
#define FIN 32
#define DEG 16
#define INDIM 288
#define BM 128
#define NTILES ((NVV + BM - 1) / BM)   // 391
#define GRID_TC 148

// W^T (k-major) smem: 288 k-rows x 136 n-cols bf16, stride 272 B (phase-distinct for ldmatrix)
// Act chunk smem: 128 m-rows x 136 k-cols bf16, stride 272 B
#define WSB 272
#define SM_WHI 0
#define SM_WLO 78336
#define SM_ACTHI 156672
#define SM_ACTLO 191488
#define SM_BIAS 226304
#define SM_DYN 226816

// ---------------------------------------------------------------------------
__device__ __align__(16) unsigned short g_wh[2][288 * 136];
__device__ __align__(16) unsigned short g_wl[2][288 * 136];
__device__ __align__(256) float g_bufs[4][(size_t)NVV * DD];
__device__ float g_colsum[DD];
__device__ int g_is64;

__device__ __forceinline__ uint32_t smem_u32(const void* p) {
    uint32_t a;
    asm("{ .reg .u64 t; cvta.to.shared.u64 t, %1; cvt.u32.u64 %0, t; }" : "=r"(a) : "l"(p));
    return a;
}
__device__ __forceinline__ void ldsm_x4(uint32_t* r, uint32_t addr) {
    asm volatile("ldmatrix.sync.aligned.m8n8.x4.shared.b16 {%0,%1,%2,%3}, [%4];"
                 : "=r"(r[0]), "=r"(r[1]), "=r"(r[2]), "=r"(r[3]) : "r"(addr));
}
__device__ __forceinline__ void ldsm_x4t(uint32_t* r, uint32_t addr) {
    asm volatile("ldmatrix.sync.aligned.m8n8.x4.trans.shared.b16 {%0,%1,%2,%3}, [%4];"
                 : "=r"(r[0]), "=r"(r[1]), "=r"(r[2]), "=r"(r[3]) : "r"(addr));
}
__device__ __forceinline__ void mma_bf16(float* d, const uint32_t* a, uint32_t b0, uint32_t b1) {
    asm volatile("mma.sync.aligned.m16n8k16.row.col.f32.bf16.bf16.f32 "
                 "{%0,%1,%2,%3}, {%4,%5,%6,%7}, {%8,%9}, {%0,%1,%2,%3};"
                 : "+f"(d[0]), "+f"(d[1]), "+f"(d[2]), "+f"(d[3])
                 : "r"(a[0]), "r"(a[1]), "r"(a[2]), "r"(a[3]), "r"(b0), "r"(b1));
}
// pack two fp32 -> bf16x2 (lo half = a, hi half = b)
__device__ __forceinline__ uint32_t pack_bf2(float a, float b) {
    uint32_t r;
    asm("cvt.rn.bf16x2.f32 %0, %1, %2;" : "=r"(r) : "f"(b), "f"(a));
    return r;
}
// split float4 -> hi bf16x2 pair + lo bf16x2 pair
__device__ __forceinline__ void split4(float4 v, uint2& hi, uint2& lo) {
    uint32_t h01 = pack_bf2(v.x, v.y);
    uint32_t h23 = pack_bf2(v.z, v.w);
    float hx = __uint_as_float(h01 << 16);
    float hy = __uint_as_float(h01 & 0xffff0000u);
    float hz = __uint_as_float(h23 << 16);
    float hw = __uint_as_float(h23 & 0xffff0000u);
    hi.x = h01; hi.y = h23;
    lo.x = pack_bf2(v.x - hx, v.y - hy);
    lo.y = pack_bf2(v.z - hz, v.w - hw);
}

// ---------------------------------------------------------------------------
__global__ void detect_kernel(const int* __restrict__ idx32) {
    if (threadIdx.x == 0) {
        int nz = 0;
#pragma unroll
        for (int i = 0; i < 64; i++) nz |= idx32[2 * i + 1];
        g_is64 = (nz == 0) ? 1 : 0;
    }
}
__global__ void zero_colsum() { if (threadIdx.x < DD) g_colsum[threadIdx.x] = 0.f; }

// Pre-split W into k-major padded hi/lo images. block 0 = W_v, block 1 = W_c.
__global__ void prep_w(const float* __restrict__ Wv, const float* __restrict__ Wc) {
    int which = blockIdx.x;
    const float* W = which ? Wc : Wv;
    for (int e = threadIdx.x; e < 288 * 136; e += blockDim.x) {
        int k = e / 136, nn = e - k * 136;
        float w = (nn < 128) ? W[nn * INDIM + k] : 0.f;
        uint32_t h = pack_bf2(w, 0.f);
        float hf = __uint_as_float(h << 16);
        uint32_t l = pack_bf2(w - hf, 0.f);
        g_wh[which][e] = (unsigned short)(h & 0xffff);
        g_wl[which][e] = (unsigned short)(l & 0xffff);
    }
}

// ---------------------------------------------------------------------------
__global__ void init_embed(const float* __restrict__ feat,
                           const float* __restrict__ W,
                           const float* __restrict__ b,
                           int out_sel, int n) {
    __shared__ float sF[64][FIN];
    float* out = g_bufs[out_sel];
    int row0 = blockIdx.x * 64;
    int tid = threadIdx.x;
    for (int i = tid; i < 64 * FIN; i += 256) {
        int r = i >> 5, k = i & 31;
        int gr = row0 + r;
        sF[r][k] = (gr < n) ? feat[(size_t)gr * FIN + k] : 0.f;
    }
    __syncthreads();
    int col = tid & 127;
    int rh = tid >> 7;
    float w[FIN];
#pragma unroll
    for (int k = 0; k < FIN; k++) w[k] = W[col * FIN + k];
    float bias = b[col];
    int rbeg = rh * 32, rend = rbeg + 32;
    if (row0 + rend > n) rend = (n > row0) ? (n - row0) : 0;
    for (int r = rbeg; r < rend; r++) {
        float acc = bias;
#pragma unroll
        for (int k = 0; k < FIN; k++) acc = fmaf(sF[r][k], w[k], acc);
        out[(size_t)(row0 + r) * DD + col] = acc;
    }
}

// ---------------------------------------------------------------------------
// Persistent tensor layer: per tile, 3 chunks (agg k0-127 | self k128-255 |
// feat k256-287). Fill chunk (gather+bf16 split into smem), then HMMA it.
// ---------------------------------------------------------------------------
__global__ __launch_bounds__(256, 1)
void layer_tc(int agg_sel, int self_sel, int out_sel, int which,
              const float* __restrict__ feat,
              const int* __restrict__ idx32,
              const float* __restrict__ b, int n)
{
    extern __shared__ char sm[];
    uint32_t smb = smem_u32(sm);

    const float* aggsrc = g_bufs[agg_sel];
    const float* selfp  = g_bufs[self_sel];
    float* out = g_bufs[out_sel];

    int tid = threadIdx.x, wid = tid >> 5, lane = tid & 31;
    int wm = wid >> 1, wn = wid & 1;          // warp grid 4 (m) x 2 (n)
    int istride = g_is64 ? 2 : 1;

    // ---- stage W hi/lo + bias into smem (once per CTA) ----
    {
        const uint4* sh = (const uint4*)g_wh[which];
        const uint4* sl = (const uint4*)g_wl[which];
        uint4* dh = (uint4*)(sm + SM_WHI);
        uint4* dl = (uint4*)(sm + SM_WLO);
        for (int i = tid; i < 78336 / 16; i += 256) { dh[i] = sh[i]; dl[i] = sl[i]; }
        if (tid < 128) ((float*)(sm + SM_BIAS))[tid] = b[tid];
    }
    __syncthreads();
    const float* sbias = (const float*)(sm + SM_BIAS);

    int rsel = lane & 15, csel = lane >> 4;
    uint32_t aAddrBase = smb + SM_ACTHI + (uint32_t)(csel * 16);         // + row*272 + klocal*2
    uint32_t bAddrBase = smb + SM_WHI + (uint32_t)(rsel * WSB + csel * 16);

    for (int tile = blockIdx.x; tile < NTILES; tile += GRID_TC) {
        int row0 = tile * BM;
        __syncthreads();   // previous tile's ldmatrix/epilogue done before refill

        float acc[2][8][4];
#pragma unroll
        for (int mt = 0; mt < 2; mt++)
#pragma unroll
            for (int nt = 0; nt < 8; nt++)
#pragma unroll
                for (int q = 0; q < 4; q++) acc[mt][nt][q] = 0.f;

#pragma unroll 1
        for (int chunk = 0; chunk < 3; chunk++) {
            // ==== fill chunk (warp per row, lane covers 4 cols) ====
            if (chunk == 0) {
                for (int r = wid; r < BM; r += 8) {
                    int gr = row0 + r;
                    float4 v = make_float4(0.f, 0.f, 0.f, 0.f);
                    if (gr < n) {
                        const int* ip = idx32 + (size_t)gr * DEG * istride;
                        int srcs[DEG];
#pragma unroll
                        for (int j = 0; j < DEG; j++) srcs[j] = ip[j * istride];
#pragma unroll
                        for (int j = 0; j < DEG; j++) {
                            float4 t = reinterpret_cast<const float4*>(
                                aggsrc + (size_t)srcs[j] * DD)[lane];
                            v.x += t.x; v.y += t.y; v.z += t.z; v.w += t.w;
                        }
                    }
                    uint2 hi, lo; split4(v, hi, lo);
                    *(uint2*)(sm + SM_ACTHI + r * WSB + lane * 8) = hi;
                    *(uint2*)(sm + SM_ACTLO + r * WSB + lane * 8) = lo;
                }
            } else if (chunk == 1) {
                for (int r = wid; r < BM; r += 8) {
                    int gr = row0 + r;
                    float4 v = (gr < n)
                        ? reinterpret_cast<const float4*>(selfp + (size_t)gr * DD)[lane]
                        : make_float4(0.f, 0.f, 0.f, 0.f);
                    uint2 hi, lo; split4(v, hi, lo);
                    *(uint2*)(sm + SM_ACTHI + r * WSB + lane * 8) = hi;
                    *(uint2*)(sm + SM_ACTLO + r * WSB + lane * 8) = lo;
                }
            } else {
                for (int r = wid; r < BM; r += 8) {
                    int gr = row0 + r;
                    if (lane < 8) {
                        float4 v = (gr < n)
                            ? reinterpret_cast<const float4*>(feat + (size_t)gr * FIN)[lane]
                            : make_float4(0.f, 0.f, 0.f, 0.f);
                        uint2 hi, lo; split4(v, hi, lo);
                        *(uint2*)(sm + SM_ACTHI + r * WSB + lane * 8) = hi;
                        *(uint2*)(sm + SM_ACTLO + r * WSB + lane * 8) = lo;
                    }
                }
            }
            __syncthreads();

            // ==== MMA over this chunk ====
            int kbase_w = chunk * 128;
            int nk = (chunk == 2) ? 2 : 8;
#pragma unroll 1
            for (int ks = 0; ks < nk; ks++) {
                int klocal = ks * 16;
                uint32_t ahi[2][4], alo[2][4], bhi[4][4], blo[4][4];
#pragma unroll
                for (int mt = 0; mt < 2; mt++) {
                    uint32_t ra = aAddrBase
                        + (uint32_t)((32 * wm + 16 * mt + rsel) * WSB + klocal * 2);
                    ldsm_x4(ahi[mt], ra);
                    ldsm_x4(alo[mt], ra + (SM_ACTLO - SM_ACTHI));
                }
#pragma unroll
                for (int np = 0; np < 4; np++) {
                    uint32_t rb = bAddrBase
                        + (uint32_t)((kbase_w + klocal) * WSB + (64 * wn + 16 * np) * 2);
                    ldsm_x4t(bhi[np], rb);
                    ldsm_x4t(blo[np], rb + (SM_WLO - SM_WHI));
                }
                // term 1: Ahi * Whi
#pragma unroll
                for (int mt = 0; mt < 2; mt++)
#pragma unroll
                    for (int nt = 0; nt < 8; nt++)
                        mma_bf16(acc[mt][nt], ahi[mt],
                                 bhi[nt >> 1][2 * (nt & 1)], bhi[nt >> 1][2 * (nt & 1) + 1]);
                // term 2: Ahi * Wlo
#pragma unroll
                for (int mt = 0; mt < 2; mt++)
#pragma unroll
                    for (int nt = 0; nt < 8; nt++)
                        mma_bf16(acc[mt][nt], ahi[mt],
                                 blo[nt >> 1][2 * (nt & 1)], blo[nt >> 1][2 * (nt & 1) + 1]);
                // term 3: Alo * Whi
#pragma unroll
                for (int mt = 0; mt < 2; mt++)
#pragma unroll
                    for (int nt = 0; nt < 8; nt++)
                        mma_bf16(acc[mt][nt], alo[mt],
                                 bhi[nt >> 1][2 * (nt & 1)], bhi[nt >> 1][2 * (nt & 1) + 1]);
            }
            if (chunk < 2) __syncthreads();  // before refilling Act buffer
        }

        // ==== epilogue: acc regs -> gmem with bias ====
        int r_lo = lane >> 2;
        int cpair = (lane & 3) * 2;
#pragma unroll
        for (int mt = 0; mt < 2; mt++) {
            int ra = row0 + 32 * wm + 16 * mt + r_lo;
#pragma unroll
            for (int nt = 0; nt < 8; nt++) {
                int col = 64 * wn + 8 * nt + cpair;
                float b0 = sbias[col], b1 = sbias[col + 1];
                if (ra < n) {
                    float2 v = make_float2(acc[mt][nt][0] + b0, acc[mt][nt][1] + b1);
                    *(float2*)(out + (size_t)ra * DD + col) = v;
                }
                if (ra + 8 < n) {
                    float2 v = make_float2(acc[mt][nt][2] + b0, acc[mt][nt][3] + b1);
                    *(float2*)(out + (size_t)(ra + 8) * DD + col) = v;
                }
            }
        }
    }
}

// ---------------------------------------------------------------------------
__global__ void colsum_kernel(int lv_sel, int n) {
    const float* lv = g_bufs[lv_sel];
    __shared__ float s[DD];
    int tid = threadIdx.x;
    int col = tid & (DD - 1);
    int half = tid >> 7;
    int r0 = blockIdx.x * 128 + half * 64;
    int r1 = r0 + 64; if (r1 > n) r1 = n;
    float acc = 0.f;
    for (int r = r0; r < r1; r++) acc += lv[(size_t)r * DD + col];
    if (half) s[col] = acc;
    __syncthreads();
    if (!half) atomicAdd(&g_colsum[col], acc + s[col]);
}

__global__ void final_kernel(int lv_sel, const float* __restrict__ Wq,
                             const float* __restrict__ bq,
                             float* __restrict__ Q, int n) {
    const float* lv = g_bufs[lv_sel];
    __shared__ float sW[DD];
    __shared__ float s_s;
    int tid = threadIdx.x;
    if (tid < DD) sW[tid] = Wq[DD + tid];
    if (tid < 32) {
        float p = 0.f;
#pragma unroll
        for (int t = 0; t < 4; t++) p += g_colsum[tid + 32 * t] * Wq[tid + 32 * t];
#pragma unroll
        for (int o = 16; o > 0; o >>= 1) p += __shfl_xor_sync(0xffffffffu, p, o);
        if (tid == 0) s_s = p + bq[0];
    }
    __syncthreads();
    int warp = tid >> 5, lane = tid & 31;
    int base = blockIdx.x * 64 + warp * 8;
    for (int i = 0; i < 8; i++) {
        int row = base + i;
        if (row >= n) break;
        const float* rp = lv + (size_t)row * DD;
        float p = rp[lane]      * sW[lane]
                + rp[lane + 32] * sW[lane + 32]
                + rp[lane + 64] * sW[lane + 64]
                + rp[lane + 96] * sW[lane + 96];
#pragma unroll
        for (int o = 16; o > 0; o >>= 1) p += __shfl_xor_sync(0xffffffffu, p, o);
        if (lane == 0) Q[row] = s_s + p;
    }
}

// ---------------------------------------------------------------------------
extern "C" void kernel_launch(void* const* d_in, const int* in_sizes, int n_in,
                              void* d_out, int out_size) {
    const float* x    = (const float*)d_in[0];
    const int*   vci  = (const int*)d_in[1];
    const int*   cvi  = (const int*)d_in[2];
    const float* W_iv = (const float*)d_in[3];
    const float* b_iv = (const float*)d_in[4];
    const float* W_ic = (const float*)d_in[5];
    const float* b_ic = (const float*)d_in[6];
    const float* W_v  = (const float*)d_in[7];
    const float* b_v  = (const float*)d_in[8];
    const float* W_c  = (const float*)d_in[9];
    const float* b_c  = (const float*)d_in[10];
    const float* W_q  = (const float*)d_in[11];
    const float* b_q  = (const float*)d_in[12];
    float* Q = (float*)d_out;

    cudaFuncSetAttribute(layer_tc,
                         cudaFuncAttributeMaxDynamicSharedMemorySize, SM_DYN);

    const float* var_feat = x;
    const float* con_feat = x + (size_t)NVV * FIN;

    detect_kernel<<<1, 32>>>(vci);
    prep_w<<<2, 256>>>(W_v, W_c);
    init_embed<<<(NVV + 63) / 64, 256>>>(var_feat, W_iv, b_iv, 0, NVV);
    init_embed<<<(NVV + 63) / 64, 256>>>(con_feat, W_ic, b_ic, 2, NVV);

    int lv = 0, lc = 2;
    for (int t = 0; t < 3; t++) {
        int nlc = 5 - lc, nlv = 1 - lv;
        // lc_new = W_c * [gather(lv, cvi), lc, con_feat] + b_c   (which=1)
        layer_tc<<<GRID_TC, 256, SM_DYN>>>(lv, lc, nlc, 1, con_feat, cvi, b_c, NVV);
        // lv_new = W_v * [gather(lc_old, vci), lv, var_feat] + b_v (which=0)
        layer_tc<<<GRID_TC, 256, SM_DYN>>>(lc, lv, nlv, 0, var_feat, vci, b_v, NVV);
        lv = nlv; lc = nlc;
    }

    zero_colsum<<<1, 128>>>();
    colsum_kernel<<<(NVV + 127) / 128, 256>>>(lv, NVV);
    final_kernel<<<(NVV + 63) / 64, 256>>>(lv, W_q, b_q, Q, NVV);
}

// round 5
// speedup vs baseline: 1.8914x; 1.2515x over previous
#include <cuda_runtime.h>
#include <cuda_bf16.h>
#include <cstdint>

#define NVV 50000
#define DD 128
#define FIN 32
#define DEG 16
#define INDIM 288
#define GRID_TC 148

#define BM32 32
#define NT32 ((NVV + BM32 - 1) / BM32)   // 1563

// W^T (k-major): 288 k-rows x 136 n-cols bf16, stride 272 B (validated R3)
#define WSB 272
// Act slab: 32 rows x K=288 bf16 (+pad), stride 592 B (16-aligned, phase-distinct).
#define ACT_STR 592
#define ACT_IMG (32 * ACT_STR)            // 18944
#define ACT_SLAB (2 * ACT_IMG)            // 37888 (hi | lo)

#define SM_WHI 0
#define SM_WLO 78336
#define SM_ACT 156672
#define SM_DYN (SM_ACT + 2 * ACT_SLAB)    // 232448 == opt-in max

// named barriers: 1+slot = "full", 3+slot = "empty"
#define BAR_SYNC(id)   asm volatile("bar.sync %0, 512;"   :: "r"(id) : "memory")
#define BAR_ARRIVE(id) asm volatile("bar.arrive %0, 512;" :: "r"(id) : "memory")

// ---------------------------------------------------------------------------
__device__ __align__(16) unsigned short g_wh[2][288 * 136];
__device__ __align__(16) unsigned short g_wl[2][288 * 136];
__device__ __align__(256) float g_bufs[4][(size_t)NVV * DD];
__device__ float g_colsum[DD];
__device__ int g_is64;

__device__ __forceinline__ uint32_t smem_u32(const void* p) {
    uint32_t a;
    asm("{ .reg .u64 t; cvta.to.shared.u64 t, %1; cvt.u32.u64 %0, t; }" : "=r"(a) : "l"(p));
    return a;
}
__device__ __forceinline__ void ldsm_x4(uint32_t* r, uint32_t addr) {
    asm volatile("ldmatrix.sync.aligned.m8n8.x4.shared.b16 {%0,%1,%2,%3}, [%4];"
                 : "=r"(r[0]), "=r"(r[1]), "=r"(r[2]), "=r"(r[3]) : "r"(addr));
}
__device__ __forceinline__ void ldsm_x4t(uint32_t* r, uint32_t addr) {
    asm volatile("ldmatrix.sync.aligned.m8n8.x4.trans.shared.b16 {%0,%1,%2,%3}, [%4];"
                 : "=r"(r[0]), "=r"(r[1]), "=r"(r[2]), "=r"(r[3]) : "r"(addr));
}
__device__ __forceinline__ void mma_bf16(float* d, const uint32_t* a, uint32_t b0, uint32_t b1) {
    asm volatile("mma.sync.aligned.m16n8k16.row.col.f32.bf16.bf16.f32 "
                 "{%0,%1,%2,%3}, {%4,%5,%6,%7}, {%8,%9}, {%0,%1,%2,%3};"
                 : "+f"(d[0]), "+f"(d[1]), "+f"(d[2]), "+f"(d[3])
                 : "r"(a[0]), "r"(a[1]), "r"(a[2]), "r"(a[3]), "r"(b0), "r"(b1));
}
__device__ __forceinline__ uint32_t pack_bf2(float a, float b) {
    uint32_t r;
    asm("cvt.rn.bf16x2.f32 %0, %1, %2;" : "=r"(r) : "f"(b), "f"(a));
    return r;
}
__device__ __forceinline__ void split4(float4 v, uint2& hi, uint2& lo) {
    uint32_t h01 = pack_bf2(v.x, v.y);
    uint32_t h23 = pack_bf2(v.z, v.w);
    float hx = __uint_as_float(h01 << 16);
    float hy = __uint_as_float(h01 & 0xffff0000u);
    float hz = __uint_as_float(h23 << 16);
    float hw = __uint_as_float(h23 & 0xffff0000u);
    hi.x = h01; hi.y = h23;
    lo.x = pack_bf2(v.x - hx, v.y - hy);
    lo.y = pack_bf2(v.z - hz, v.w - hw);
}

// ---------------------------------------------------------------------------
__global__ void detect_kernel(const int* __restrict__ idx32) {
    if (threadIdx.x == 0) {
        int nz = 0;
#pragma unroll
        for (int i = 0; i < 64; i++) nz |= idx32[2 * i + 1];
        g_is64 = (nz == 0) ? 1 : 0;
    }
}
__global__ void zero_colsum() { if (threadIdx.x < DD) g_colsum[threadIdx.x] = 0.f; }

__global__ void prep_w(const float* __restrict__ Wv, const float* __restrict__ Wc) {
    int which = blockIdx.x;
    const float* W = which ? Wc : Wv;
    for (int e = threadIdx.x; e < 288 * 136; e += blockDim.x) {
        int k = e / 136, nn = e - k * 136;
        float w = (nn < 128) ? W[nn * INDIM + k] : 0.f;
        uint32_t h = pack_bf2(w, 0.f);
        float hf = __uint_as_float(h << 16);
        uint32_t l = pack_bf2(w - hf, 0.f);
        g_wh[which][e] = (unsigned short)(h & 0xffff);
        g_wl[which][e] = (unsigned short)(l & 0xffff);
    }
}

// ---------------------------------------------------------------------------
// initial embedding: 4 independent accumulator chains per thread.
// ---------------------------------------------------------------------------
__global__ void init_embed(const float* __restrict__ feat,
                           const float* __restrict__ W,
                           const float* __restrict__ b,
                           int out_sel, int n) {
    __shared__ float sF[64][FIN];
    float* out = g_bufs[out_sel];
    int row0 = blockIdx.x * 64;
    int tid = threadIdx.x;
    for (int i = tid; i < 64 * FIN; i += 256) {
        int r = i >> 5, k = i & 31;
        int gr = row0 + r;
        sF[r][k] = (gr < n) ? feat[(size_t)gr * FIN + k] : 0.f;
    }
    __syncthreads();
    int col = tid & 127;
    int rh = tid >> 7;
    float w[FIN];
#pragma unroll
    for (int k = 0; k < FIN; k++) w[k] = W[col * FIN + k];
    float bias = b[col];
    int rbeg = rh * 32;
#pragma unroll 1
    for (int r = rbeg; r < rbeg + 32; r += 4) {
        float a0 = bias, a1 = bias, a2 = bias, a3 = bias;
#pragma unroll
        for (int k = 0; k < FIN; k++) {
            float wk = w[k];
            a0 = fmaf(sF[r][k],     wk, a0);
            a1 = fmaf(sF[r + 1][k], wk, a1);
            a2 = fmaf(sF[r + 2][k], wk, a2);
            a3 = fmaf(sF[r + 3][k], wk, a3);
        }
        int gr = row0 + r;
        if (gr < n)     out[(size_t)gr * DD + col] = a0;
        if (gr + 1 < n) out[(size_t)(gr + 1) * DD + col] = a1;
        if (gr + 2 < n) out[(size_t)(gr + 2) * DD + col] = a2;
        if (gr + 3 < n) out[(size_t)(gr + 3) * DD + col] = a3;
    }
}

// ---------------------------------------------------------------------------
// Warp-specialized layer: warps 8-15 produce (gather + bf16 split + STS into
// 2-slot Act ring), warps 0-7 consume (ldmatrix + 3-term bf16 HMMA + epilogue).
// ---------------------------------------------------------------------------
__global__ __launch_bounds__(512, 1)
void layer_ws(int agg_sel, int self_sel, int out_sel, int which,
              const float* __restrict__ feat,
              const int* __restrict__ idx32,
              const float* __restrict__ b, int n)
{
    extern __shared__ char sm[];
    uint32_t smb = smem_u32(sm);

    const float* aggsrc = g_bufs[agg_sel];
    const float* selfp  = g_bufs[self_sel];
    float* out = g_bufs[out_sel];

    int tid = threadIdx.x, wid = tid >> 5, lane = tid & 31;
    int istride = g_is64 ? 2 : 1;

    // ---- stage W hi/lo (all 512 threads) ----
    {
        const uint4* sh = (const uint4*)g_wh[which];
        const uint4* sl = (const uint4*)g_wl[which];
        uint4* dh = (uint4*)(sm + SM_WHI);
        uint4* dl = (uint4*)(sm + SM_WLO);
        for (int i = tid; i < 78336 / 16; i += 512) { dh[i] = sh[i]; dl[i] = sl[i]; }
    }
    __syncthreads();

    if (wid >= 8) {
        // ================= PRODUCERS =================
        int pw = wid - 8;              // 0..7, owns rows pw*4 .. pw*4+3
        int it = 0;
        for (int tile = blockIdx.x; tile < NT32; tile += GRID_TC, it++) {
            int slot = it & 1;
            BAR_SYNC(3 + slot);        // wait slot empty (primed by consumers)
            char* act = sm + SM_ACT + slot * ACT_SLAB;
            int row0 = tile * BM32;
#pragma unroll 1
            for (int rr = 0; rr < 4; rr++) {
                int r = pw * 4 + rr;
                int gr = row0 + r;
                if (gr < n) {
                    const int* ip = idx32 + (size_t)gr * DEG * istride;
                    int srcs[DEG];
#pragma unroll
                    for (int j = 0; j < DEG; j++) srcs[j] = ip[j * istride];
                    float4 v = make_float4(0.f, 0.f, 0.f, 0.f);
#pragma unroll
                    for (int j = 0; j < DEG; j++) {
                        float4 t = reinterpret_cast<const float4*>(
                            aggsrc + (size_t)srcs[j] * DD)[lane];
                        v.x += t.x; v.y += t.y; v.z += t.z; v.w += t.w;
                    }
                    uint2 hi, lo; split4(v, hi, lo);
                    char* rowp = act + r * ACT_STR;
                    *(uint2*)(rowp + lane * 8) = hi;
                    *(uint2*)(rowp + ACT_IMG + lane * 8) = lo;
                    // self: k 128..255 -> byte 256
                    float4 sv = reinterpret_cast<const float4*>(selfp + (size_t)gr * DD)[lane];
                    split4(sv, hi, lo);
                    *(uint2*)(rowp + 256 + lane * 8) = hi;
                    *(uint2*)(rowp + ACT_IMG + 256 + lane * 8) = lo;
                    // feat: k 256..287 -> byte 512 (lanes 0-7)
                    if (lane < 8) {
                        float4 fv = reinterpret_cast<const float4*>(feat + (size_t)gr * FIN)[lane];
                        split4(fv, hi, lo);
                        *(uint2*)(rowp + 512 + lane * 8) = hi;
                        *(uint2*)(rowp + ACT_IMG + 512 + lane * 8) = lo;
                    }
                }
            }
            BAR_ARRIVE(1 + slot);      // mark slot full
        }
    } else {
        // ================= CONSUMERS =================
        int wm = wid >> 2, wn = wid & 3;   // rows 16*wm..+15, cols 32*wn..+31
        int rsel = lane & 15, csel = lane >> 4;
        // prime both slots as empty
        BAR_ARRIVE(3); BAR_ARRIVE(4);

        uint32_t aOff = (uint32_t)((16 * wm + rsel) * ACT_STR + csel * 16);
        uint32_t bBase = smb + SM_WHI + (uint32_t)(rsel * WSB + csel * 16 + 64 * wn);

        // bias pairs in registers (tile-invariant)
        int cpair = (lane & 3) * 2;
        float2 bb[4];
#pragma unroll
        for (int nt = 0; nt < 4; nt++) {
            int col = 32 * wn + 8 * nt + cpair;
            bb[nt].x = b[col]; bb[nt].y = b[col + 1];
        }

        int it = 0;
        for (int tile = blockIdx.x; tile < NT32; tile += GRID_TC, it++) {
            int slot = it & 1;
            BAR_SYNC(1 + slot);        // wait slot full
            uint32_t aBase = smb + SM_ACT + (uint32_t)(slot * ACT_SLAB) + aOff;

            float acc[4][4];
#pragma unroll
            for (int nt = 0; nt < 4; nt++)
#pragma unroll
                for (int q = 0; q < 4; q++) acc[nt][q] = 0.f;

#pragma unroll 1
            for (int ks = 0; ks < 18; ks++) {
                uint32_t ahi[4], alo[4], bhi[2][4], blo[2][4];
                uint32_t ra = aBase + (uint32_t)(ks * 32);
                ldsm_x4(ahi, ra);
                ldsm_x4(alo, ra + ACT_IMG);
#pragma unroll
                for (int np = 0; np < 2; np++) {
                    uint32_t rb = bBase + (uint32_t)(ks * 16 * WSB + 32 * np);
                    ldsm_x4t(bhi[np], rb);
                    ldsm_x4t(blo[np], rb + (SM_WLO - SM_WHI));
                }
#pragma unroll
                for (int nt = 0; nt < 4; nt++)
                    mma_bf16(acc[nt], ahi, bhi[nt >> 1][2 * (nt & 1)], bhi[nt >> 1][2 * (nt & 1) + 1]);
#pragma unroll
                for (int nt = 0; nt < 4; nt++)
                    mma_bf16(acc[nt], ahi, blo[nt >> 1][2 * (nt & 1)], blo[nt >> 1][2 * (nt & 1) + 1]);
#pragma unroll
                for (int nt = 0; nt < 4; nt++)
                    mma_bf16(acc[nt], alo, bhi[nt >> 1][2 * (nt & 1)], bhi[nt >> 1][2 * (nt & 1) + 1]);
            }
            BAR_ARRIVE(3 + slot);      // slot free (acc in regs)

            // epilogue
            int row0 = tile * BM32;
            int r_lo = lane >> 2;
            int ra0 = row0 + 16 * wm + r_lo;
#pragma unroll
            for (int nt = 0; nt < 4; nt++) {
                int col = 32 * wn + 8 * nt + cpair;
                if (ra0 < n) {
                    float2 v = make_float2(acc[nt][0] + bb[nt].x, acc[nt][1] + bb[nt].y);
                    *(float2*)(out + (size_t)ra0 * DD + col) = v;
                }
                if (ra0 + 8 < n) {
                    float2 v = make_float2(acc[nt][2] + bb[nt].x, acc[nt][3] + bb[nt].y);
                    *(float2*)(out + (size_t)(ra0 + 8) * DD + col) = v;
                }
            }
        }
    }
}

// ---------------------------------------------------------------------------
__global__ void colsum_kernel(int lv_sel, int n) {
    const float* lv = g_bufs[lv_sel];
    __shared__ float s[DD];
    int tid = threadIdx.x;
    int col = tid & (DD - 1);
    int half = tid >> 7;
    int r0 = blockIdx.x * 128 + half * 64;
    int r1 = r0 + 64; if (r1 > n) r1 = n;
    float acc = 0.f;
    for (int r = r0; r < r1; r++) acc += lv[(size_t)r * DD + col];
    if (half) s[col] = acc;
    __syncthreads();
    if (!half) atomicAdd(&g_colsum[col], acc + s[col]);
}

__global__ void final_kernel(int lv_sel, const float* __restrict__ Wq,
                             const float* __restrict__ bq,
                             float* __restrict__ Q, int n) {
    const float* lv = g_bufs[lv_sel];
    __shared__ float sW[DD];
    __shared__ float s_s;
    int tid = threadIdx.x;
    if (tid < DD) sW[tid] = Wq[DD + tid];
    if (tid < 32) {
        float p = 0.f;
#pragma unroll
        for (int t = 0; t < 4; t++) p += g_colsum[tid + 32 * t] * Wq[tid + 32 * t];
#pragma unroll
        for (int o = 16; o > 0; o >>= 1) p += __shfl_xor_sync(0xffffffffu, p, o);
        if (tid == 0) s_s = p + bq[0];
    }
    __syncthreads();
    int warp = tid >> 5, lane = tid & 31;
    int base = blockIdx.x * 64 + warp * 8;
    for (int i = 0; i < 8; i++) {
        int row = base + i;
        if (row >= n) break;
        const float* rp = lv + (size_t)row * DD;
        float p = rp[lane]      * sW[lane]
                + rp[lane + 32] * sW[lane + 32]
                + rp[lane + 64] * sW[lane + 64]
                + rp[lane + 96] * sW[lane + 96];
#pragma unroll
        for (int o = 16; o > 0; o >>= 1) p += __shfl_xor_sync(0xffffffffu, p, o);
        if (lane == 0) Q[row] = s_s + p;
    }
}

// ---------------------------------------------------------------------------
extern "C" void kernel_launch(void* const* d_in, const int* in_sizes, int n_in,
                              void* d_out, int out_size) {
    const float* x    = (const float*)d_in[0];
    const int*   vci  = (const int*)d_in[1];
    const int*   cvi  = (const int*)d_in[2];
    const float* W_iv = (const float*)d_in[3];
    const float* b_iv = (const float*)d_in[4];
    const float* W_ic = (const float*)d_in[5];
    const float* b_ic = (const float*)d_in[6];
    const float* W_v  = (const float*)d_in[7];
    const float* b_v  = (const float*)d_in[8];
    const float* W_c  = (const float*)d_in[9];
    const float* b_c  = (const float*)d_in[10];
    const float* W_q  = (const float*)d_in[11];
    const float* b_q  = (const float*)d_in[12];
    float* Q = (float*)d_out;

    cudaFuncSetAttribute(layer_ws,
                         cudaFuncAttributeMaxDynamicSharedMemorySize, SM_DYN);

    const float* var_feat = x;
    const float* con_feat = x + (size_t)NVV * FIN;

    detect_kernel<<<1, 32>>>(vci);
    prep_w<<<2, 256>>>(W_v, W_c);
    init_embed<<<(NVV + 63) / 64, 256>>>(var_feat, W_iv, b_iv, 0, NVV);
    init_embed<<<(NVV + 63) / 64, 256>>>(con_feat, W_ic, b_ic, 2, NVV);

    int lv = 0, lc = 2;
    for (int t = 0; t < 3; t++) {
        int nlc = 5 - lc, nlv = 1 - lv;
        // lc_new = W_c * [gather(lv, cvi), lc, con_feat] + b_c   (which=1)
        layer_ws<<<GRID_TC, 512, SM_DYN>>>(lv, lc, nlc, 1, con_feat, cvi, b_c, NVV);
        // lv_new = W_v * [gather(lc_old, vci), lv, var_feat] + b_v (which=0)
        layer_ws<<<GRID_TC, 512, SM_DYN>>>(lc, lv, nlv, 0, var_feat, vci, b_v, NVV);
        lv = nlv; lc = nlc;
    }

    zero_colsum<<<1, 128>>>();
    colsum_kernel<<<(NVV + 127) / 128, 256>>>(lv, NVV);
    final_kernel<<<(NVV + 63) / 64, 256>>>(lv, W_q, b_q, Q, NVV);
}

// round 6
// speedup vs baseline: 2.6837x; 1.4189x over previous
#include <cuda_runtime.h>
#include <cuda_bf16.h>
#include <cstdint>

#define NVV 50000
#define DD 128
#define FIN 32
#define DEG 16
#define INDIM 288
#define GRID_TC 148
#define NBLK_SIDE (GRID_TC / 2)          // 74 persistent CTAs per side

#define BM32 32
#define NT32 ((NVV + BM32 - 1) / BM32)   // 1563

// W^T (k-major): 288 k-rows x 136 n-cols bf16, stride 272 B (validated R3/R5)
#define WSB 272
// Act slab: 32 rows x K=288 bf16 (+pad), stride 592 B (16-aligned, phase-distinct).
#define ACT_STR 592
#define ACT_IMG (32 * ACT_STR)            // 18944
#define ACT_SLAB (2 * ACT_IMG)            // 37888 (hi | lo)

#define SM_WHI 0
#define SM_WLO 78336
#define SM_ACT 156672
#define SM_DYN (SM_ACT + 2 * ACT_SLAB)    // 232448 == opt-in max

// named barriers: 1+slot = "full", 3+slot = "empty"
#define BAR_SYNC(id)   asm volatile("bar.sync %0, 512;"   :: "r"(id) : "memory")
#define BAR_ARRIVE(id) asm volatile("bar.arrive %0, 512;" :: "r"(id) : "memory")

// ---------------------------------------------------------------------------
__device__ __align__(16) unsigned short g_wh[2][288 * 136];
__device__ __align__(16) unsigned short g_wl[2][288 * 136];
__device__ __align__(256) float g_bufs[4][(size_t)NVV * DD];
__device__ float g_colsum[DD];
__device__ int g_is64;

__device__ __forceinline__ uint32_t smem_u32(const void* p) {
    uint32_t a;
    asm("{ .reg .u64 t; cvta.to.shared.u64 t, %1; cvt.u32.u64 %0, t; }" : "=r"(a) : "l"(p));
    return a;
}
__device__ __forceinline__ void ldsm_x4(uint32_t* r, uint32_t addr) {
    asm volatile("ldmatrix.sync.aligned.m8n8.x4.shared.b16 {%0,%1,%2,%3}, [%4];"
                 : "=r"(r[0]), "=r"(r[1]), "=r"(r[2]), "=r"(r[3]) : "r"(addr));
}
__device__ __forceinline__ void ldsm_x4t(uint32_t* r, uint32_t addr) {
    asm volatile("ldmatrix.sync.aligned.m8n8.x4.trans.shared.b16 {%0,%1,%2,%3}, [%4];"
                 : "=r"(r[0]), "=r"(r[1]), "=r"(r[2]), "=r"(r[3]) : "r"(addr));
}
__device__ __forceinline__ void mma_bf16(float* d, const uint32_t* a, uint32_t b0, uint32_t b1) {
    asm volatile("mma.sync.aligned.m16n8k16.row.col.f32.bf16.bf16.f32 "
                 "{%0,%1,%2,%3}, {%4,%5,%6,%7}, {%8,%9}, {%0,%1,%2,%3};"
                 : "+f"(d[0]), "+f"(d[1]), "+f"(d[2]), "+f"(d[3])
                 : "r"(a[0]), "r"(a[1]), "r"(a[2]), "r"(a[3]), "r"(b0), "r"(b1));
}
__device__ __forceinline__ uint32_t pack_bf2(float a, float b) {
    uint32_t r;
    asm("cvt.rn.bf16x2.f32 %0, %1, %2;" : "=r"(r) : "f"(b), "f"(a));
    return r;
}
__device__ __forceinline__ void split4(float4 v, uint2& hi, uint2& lo) {
    uint32_t h01 = pack_bf2(v.x, v.y);
    uint32_t h23 = pack_bf2(v.z, v.w);
    float hx = __uint_as_float(h01 << 16);
    float hy = __uint_as_float(h01 & 0xffff0000u);
    float hz = __uint_as_float(h23 << 16);
    float hw = __uint_as_float(h23 & 0xffff0000u);
    hi.x = h01; hi.y = h23;
    lo.x = pack_bf2(v.x - hx, v.y - hy);
    lo.y = pack_bf2(v.z - hz, v.w - hw);
}

// ---------------------------------------------------------------------------
__global__ void detect_kernel(const int* __restrict__ idx32) {
    if (threadIdx.x == 0) {
        int nz = 0;
#pragma unroll
        for (int i = 0; i < 64; i++) nz |= idx32[2 * i + 1];
        g_is64 = (nz == 0) ? 1 : 0;
    }
}
__global__ void zero_colsum() { if (threadIdx.x < DD) g_colsum[threadIdx.x] = 0.f; }

__global__ void prep_w(const float* __restrict__ Wv, const float* __restrict__ Wc) {
    int which = blockIdx.x;
    const float* W = which ? Wc : Wv;
    for (int e = threadIdx.x; e < 288 * 136; e += blockDim.x) {
        int k = e / 136, nn = e - k * 136;
        float w = (nn < 128) ? W[nn * INDIM + k] : 0.f;
        uint32_t h = pack_bf2(w, 0.f);
        float hf = __uint_as_float(h << 16);
        uint32_t l = pack_bf2(w - hf, 0.f);
        g_wh[which][e] = (unsigned short)(h & 0xffff);
        g_wl[which][e] = (unsigned short)(l & 0xffff);
    }
}

// ---------------------------------------------------------------------------
// HMMA initial embedding: out[128 tile] = feat(128x32) @ W^T(32x128) + b.
// Same fragment scheme as the layer consumers (3-term bf16 split).
// Act: 128 rows x 32 k bf16, stride 80 B (16-aligned, phases {0,80,32,112,
// 64,16,96,48} distinct). B: 32 k x 136 n, stride 272 (validated layout).
// ---------------------------------------------------------------------------
#define ISM_BH 0
#define ISM_BL 8704
#define ISM_ACT 17408
#define IACT_STR 80
#define IACT_IMG (128 * IACT_STR)       // 10240

__global__ __launch_bounds__(256, 1)
void init_mma(const float* __restrict__ feat,
              const float* __restrict__ W,
              const float* __restrict__ b,
              int out_sel, int n) {
    __shared__ __align__(16) char ism[ISM_ACT + 2 * IACT_IMG];   // 37888 B
    uint32_t smb = smem_u32(ism);
    float* out = g_bufs[out_sel];
    int tid = threadIdx.x, wid = tid >> 5, lane = tid & 31;
    int row0 = blockIdx.x * 128;

    // stage W^T hi/lo (32 k x 136 n)
    for (int e = tid; e < 32 * 136; e += 256) {
        int k = e / 136, nn = e - k * 136;
        float w = (nn < 128) ? W[nn * FIN + k] : 0.f;
        uint32_t h = pack_bf2(w, 0.f);
        float hf = __uint_as_float(h << 16);
        uint32_t l = pack_bf2(w - hf, 0.f);
        *(unsigned short*)(ism + ISM_BH + k * WSB + nn * 2) = (unsigned short)(h & 0xffff);
        *(unsigned short*)(ism + ISM_BL + k * WSB + nn * 2) = (unsigned short)(l & 0xffff);
    }

    // stage feat tile: thread t -> row t/2, half t&1 (16 floats)
    {
        int r = tid >> 1, half = tid & 1;
        int gr = row0 + r;
        char* rowp = ism + ISM_ACT + r * IACT_STR + half * 32;
#pragma unroll
        for (int i = 0; i < 4; i++) {
            float4 v = (gr < n)
                ? reinterpret_cast<const float4*>(feat + (size_t)gr * FIN)[half * 4 + i]
                : make_float4(0.f, 0.f, 0.f, 0.f);
            uint2 hi, lo; split4(v, hi, lo);
            *(uint2*)(rowp + i * 8) = hi;
            *(uint2*)(rowp + IACT_IMG + i * 8) = lo;
        }
    }
    __syncthreads();

    // HMMA: 8 warps = 4(m) x 2(n); per warp 2 mt x 8 nt, K=32 (2 ksteps)
    int wm = wid >> 1, wn = wid & 1;
    int rsel = lane & 15, csel = lane >> 4;
    uint32_t aBase = smb + ISM_ACT + (uint32_t)((32 * wm + rsel) * IACT_STR + csel * 16);
    uint32_t bBase = smb + ISM_BH + (uint32_t)(rsel * WSB + csel * 16 + 128 * wn);

    float acc[2][8][4];
#pragma unroll
    for (int mt = 0; mt < 2; mt++)
#pragma unroll
        for (int nt = 0; nt < 8; nt++)
#pragma unroll
            for (int q = 0; q < 4; q++) acc[mt][nt][q] = 0.f;

#pragma unroll
    for (int ks = 0; ks < 2; ks++) {
        uint32_t ahi[2][4], alo[2][4], bhi[4][4], blo[4][4];
#pragma unroll
        for (int mt = 0; mt < 2; mt++) {
            uint32_t ra = aBase + (uint32_t)(16 * mt * IACT_STR + ks * 32);
            ldsm_x4(ahi[mt], ra);
            ldsm_x4(alo[mt], ra + IACT_IMG);
        }
#pragma unroll
        for (int np = 0; np < 4; np++) {
            uint32_t rb = bBase + (uint32_t)(ks * 16 * WSB + 32 * np);
            ldsm_x4t(bhi[np], rb);
            ldsm_x4t(blo[np], rb + (ISM_BL - ISM_BH));
        }
#pragma unroll
        for (int mt = 0; mt < 2; mt++)
#pragma unroll
            for (int nt = 0; nt < 8; nt++)
                mma_bf16(acc[mt][nt], ahi[mt], bhi[nt >> 1][2 * (nt & 1)], bhi[nt >> 1][2 * (nt & 1) + 1]);
#pragma unroll
        for (int mt = 0; mt < 2; mt++)
#pragma unroll
            for (int nt = 0; nt < 8; nt++)
                mma_bf16(acc[mt][nt], ahi[mt], blo[nt >> 1][2 * (nt & 1)], blo[nt >> 1][2 * (nt & 1) + 1]);
#pragma unroll
        for (int mt = 0; mt < 2; mt++)
#pragma unroll
            for (int nt = 0; nt < 8; nt++)
                mma_bf16(acc[mt][nt], alo[mt], bhi[nt >> 1][2 * (nt & 1)], bhi[nt >> 1][2 * (nt & 1) + 1]);
    }

    // epilogue
    int r_lo = lane >> 2;
    int cpair = (lane & 3) * 2;
#pragma unroll
    for (int mt = 0; mt < 2; mt++) {
        int ra = row0 + 32 * wm + 16 * mt + r_lo;
#pragma unroll
        for (int nt = 0; nt < 8; nt++) {
            int col = 64 * wn + 8 * nt + cpair;
            float b0 = b[col], b1 = b[col + 1];
            if (ra < n) {
                float2 v = make_float2(acc[mt][nt][0] + b0, acc[mt][nt][1] + b1);
                *(float2*)(out + (size_t)ra * DD + col) = v;
            }
            if (ra + 8 < n) {
                float2 v = make_float2(acc[mt][nt][2] + b0, acc[mt][nt][3] + b1);
                *(float2*)(out + (size_t)(ra + 8) * DD + col) = v;
            }
        }
    }
}

// ---------------------------------------------------------------------------
// Dual-side warp-specialized layer. Even blocks do the C side, odd blocks the
// V side (the two sides only read OLD lv/lc, so they are independent).
// Warps 8-15 produce (gather + bf16 split + STS into 2-slot ring),
// warps 0-7 consume (ldmatrix + 3-term HMMA + epilogue).
// ---------------------------------------------------------------------------
__global__ __launch_bounds__(512, 1)
void layer_dual(int lv_sel, int lc_sel, int nlv_sel, int nlc_sel,
                const float* __restrict__ vfeat, const float* __restrict__ cfeat,
                const int* __restrict__ vci, const int* __restrict__ cvi,
                const float* __restrict__ bv, const float* __restrict__ bc, int n)
{
    extern __shared__ char sm[];
    uint32_t smb = smem_u32(sm);

    int side = blockIdx.x & 1;   // 0 = C side, 1 = V side
    int blk = blockIdx.x >> 1;   // 0..73

    const float* aggsrc; const float* selfp; float* out;
    const float* feat; const int* idx32; const float* b; int which;
    if (side == 0) {  // lc_new = W_c * [gather(lv, cvi), lc, cfeat] + b_c
        aggsrc = g_bufs[lv_sel]; selfp = g_bufs[lc_sel]; out = g_bufs[nlc_sel];
        feat = cfeat; idx32 = cvi; b = bc; which = 1;
    } else {          // lv_new = W_v * [gather(lc, vci), lv, vfeat] + b_v
        aggsrc = g_bufs[lc_sel]; selfp = g_bufs[lv_sel]; out = g_bufs[nlv_sel];
        feat = vfeat; idx32 = vci; b = bv; which = 0;
    }

    int tid = threadIdx.x, wid = tid >> 5, lane = tid & 31;
    int istride = g_is64 ? 2 : 1;

    // ---- stage W hi/lo (all 512 threads) ----
    {
        const uint4* sh = (const uint4*)g_wh[which];
        const uint4* sl = (const uint4*)g_wl[which];
        uint4* dh = (uint4*)(sm + SM_WHI);
        uint4* dl = (uint4*)(sm + SM_WLO);
        for (int i = tid; i < 78336 / 16; i += 512) { dh[i] = sh[i]; dl[i] = sl[i]; }
    }
    __syncthreads();

    if (wid >= 8) {
        // ================= PRODUCERS =================
        int pw = wid - 8;              // owns rows pw*4 .. pw*4+3
        int it = 0;
        for (int tile = blk; tile < NT32; tile += NBLK_SIDE, it++) {
            int slot = it & 1;
            int row0 = tile * BM32;
            // prefetch all 4 rows' indices BEFORE waiting on the slot
            int srcs[4][DEG];
#pragma unroll
            for (int rr = 0; rr < 4; rr++) {
                int gr = row0 + pw * 4 + rr;
                const int* ip = idx32 + (size_t)(gr < n ? gr : 0) * DEG * istride;
#pragma unroll
                for (int j = 0; j < DEG; j++) srcs[rr][j] = ip[j * istride];
            }
            BAR_SYNC(3 + slot);        // wait slot empty
            char* act = sm + SM_ACT + slot * ACT_SLAB;
#pragma unroll
            for (int rr = 0; rr < 4; rr++) {
                int r = pw * 4 + rr;
                int gr = row0 + r;
                if (gr < n) {
                    float4 v = make_float4(0.f, 0.f, 0.f, 0.f);
#pragma unroll
                    for (int j = 0; j < DEG; j++) {
                        float4 t = reinterpret_cast<const float4*>(
                            aggsrc + (size_t)srcs[rr][j] * DD)[lane];
                        v.x += t.x; v.y += t.y; v.z += t.z; v.w += t.w;
                    }
                    uint2 hi, lo; split4(v, hi, lo);
                    char* rowp = act + r * ACT_STR;
                    *(uint2*)(rowp + lane * 8) = hi;
                    *(uint2*)(rowp + ACT_IMG + lane * 8) = lo;
                    float4 sv = reinterpret_cast<const float4*>(selfp + (size_t)gr * DD)[lane];
                    split4(sv, hi, lo);
                    *(uint2*)(rowp + 256 + lane * 8) = hi;
                    *(uint2*)(rowp + ACT_IMG + 256 + lane * 8) = lo;
                    if (lane < 8) {
                        float4 fv = reinterpret_cast<const float4*>(feat + (size_t)gr * FIN)[lane];
                        split4(fv, hi, lo);
                        *(uint2*)(rowp + 512 + lane * 8) = hi;
                        *(uint2*)(rowp + ACT_IMG + 512 + lane * 8) = lo;
                    }
                }
            }
            BAR_ARRIVE(1 + slot);      // mark slot full
        }
    } else {
        // ================= CONSUMERS =================
        int wm = wid >> 2, wn = wid & 3;
        int rsel = lane & 15, csel = lane >> 4;
        BAR_ARRIVE(3); BAR_ARRIVE(4);  // prime both slots empty

        uint32_t aOff = (uint32_t)((16 * wm + rsel) * ACT_STR + csel * 16);
        uint32_t bBase = smb + SM_WHI + (uint32_t)(rsel * WSB + csel * 16 + 64 * wn);

        int cpair = (lane & 3) * 2;
        float2 bb[4];
#pragma unroll
        for (int nt = 0; nt < 4; nt++) {
            int col = 32 * wn + 8 * nt + cpair;
            bb[nt].x = b[col]; bb[nt].y = b[col + 1];
        }

        int it = 0;
        for (int tile = blk; tile < NT32; tile += NBLK_SIDE, it++) {
            int slot = it & 1;
            BAR_SYNC(1 + slot);        // wait slot full
            uint32_t aBase = smb + SM_ACT + (uint32_t)(slot * ACT_SLAB) + aOff;

            float acc[4][4];
#pragma unroll
            for (int nt = 0; nt < 4; nt++)
#pragma unroll
                for (int q = 0; q < 4; q++) acc[nt][q] = 0.f;

#pragma unroll 1
            for (int ks = 0; ks < 18; ks++) {
                uint32_t ahi[4], alo[4], bhi[2][4], blo[2][4];
                uint32_t ra = aBase + (uint32_t)(ks * 32);
                ldsm_x4(ahi, ra);
                ldsm_x4(alo, ra + ACT_IMG);
#pragma unroll
                for (int np = 0; np < 2; np++) {
                    uint32_t rb = bBase + (uint32_t)(ks * 16 * WSB + 32 * np);
                    ldsm_x4t(bhi[np], rb);
                    ldsm_x4t(blo[np], rb + (SM_WLO - SM_WHI));
                }
#pragma unroll
                for (int nt = 0; nt < 4; nt++)
                    mma_bf16(acc[nt], ahi, bhi[nt >> 1][2 * (nt & 1)], bhi[nt >> 1][2 * (nt & 1) + 1]);
#pragma unroll
                for (int nt = 0; nt < 4; nt++)
                    mma_bf16(acc[nt], ahi, blo[nt >> 1][2 * (nt & 1)], blo[nt >> 1][2 * (nt & 1) + 1]);
#pragma unroll
                for (int nt = 0; nt < 4; nt++)
                    mma_bf16(acc[nt], alo, bhi[nt >> 1][2 * (nt & 1)], bhi[nt >> 1][2 * (nt & 1) + 1]);
            }
            BAR_ARRIVE(3 + slot);      // slot free (acc in regs)

            // epilogue
            int row0 = tile * BM32;
            int r_lo = lane >> 2;
            int ra0 = row0 + 16 * wm + r_lo;
#pragma unroll
            for (int nt = 0; nt < 4; nt++) {
                int col = 32 * wn + 8 * nt + cpair;
                if (ra0 < n) {
                    float2 v = make_float2(acc[nt][0] + bb[nt].x, acc[nt][1] + bb[nt].y);
                    *(float2*)(out + (size_t)ra0 * DD + col) = v;
                }
                if (ra0 + 8 < n) {
                    float2 v = make_float2(acc[nt][2] + bb[nt].x, acc[nt][3] + bb[nt].y);
                    *(float2*)(out + (size_t)(ra0 + 8) * DD + col) = v;
                }
            }
        }
    }
}

// ---------------------------------------------------------------------------
__global__ void colsum_kernel(int lv_sel, int n) {
    const float* lv = g_bufs[lv_sel];
    __shared__ float s[DD];
    int tid = threadIdx.x;
    int col = tid & (DD - 1);
    int half = tid >> 7;
    int r0 = blockIdx.x * 128 + half * 64;
    int r1 = r0 + 64; if (r1 > n) r1 = n;
    float acc = 0.f;
    for (int r = r0; r < r1; r++) acc += lv[(size_t)r * DD + col];
    if (half) s[col] = acc;
    __syncthreads();
    if (!half) atomicAdd(&g_colsum[col], acc + s[col]);
}

__global__ void final_kernel(int lv_sel, const float* __restrict__ Wq,
                             const float* __restrict__ bq,
                             float* __restrict__ Q, int n) {
    const float* lv = g_bufs[lv_sel];
    __shared__ float sW[DD];
    __shared__ float s_s;
    int tid = threadIdx.x;
    if (tid < DD) sW[tid] = Wq[DD + tid];
    if (tid < 32) {
        float p = 0.f;
#pragma unroll
        for (int t = 0; t < 4; t++) p += g_colsum[tid + 32 * t] * Wq[tid + 32 * t];
#pragma unroll
        for (int o = 16; o > 0; o >>= 1) p += __shfl_xor_sync(0xffffffffu, p, o);
        if (tid == 0) s_s = p + bq[0];
    }
    __syncthreads();
    int warp = tid >> 5, lane = tid & 31;
    int base = blockIdx.x * 64 + warp * 8;
    for (int i = 0; i < 8; i++) {
        int row = base + i;
        if (row >= n) break;
        const float* rp = lv + (size_t)row * DD;
        float p = rp[lane]      * sW[lane]
                + rp[lane + 32] * sW[lane + 32]
                + rp[lane + 64] * sW[lane + 64]
                + rp[lane + 96] * sW[lane + 96];
#pragma unroll
        for (int o = 16; o > 0; o >>= 1) p += __shfl_xor_sync(0xffffffffu, p, o);
        if (lane == 0) Q[row] = s_s + p;
    }
}

// ---------------------------------------------------------------------------
extern "C" void kernel_launch(void* const* d_in, const int* in_sizes, int n_in,
                              void* d_out, int out_size) {
    const float* x    = (const float*)d_in[0];
    const int*   vci  = (const int*)d_in[1];
    const int*   cvi  = (const int*)d_in[2];
    const float* W_iv = (const float*)d_in[3];
    const float* b_iv = (const float*)d_in[4];
    const float* W_ic = (const float*)d_in[5];
    const float* b_ic = (const float*)d_in[6];
    const float* W_v  = (const float*)d_in[7];
    const float* b_v  = (const float*)d_in[8];
    const float* W_c  = (const float*)d_in[9];
    const float* b_c  = (const float*)d_in[10];
    const float* W_q  = (const float*)d_in[11];
    const float* b_q  = (const float*)d_in[12];
    float* Q = (float*)d_out;

    cudaFuncSetAttribute(layer_dual,
                         cudaFuncAttributeMaxDynamicSharedMemorySize, SM_DYN);

    const float* var_feat = x;
    const float* con_feat = x + (size_t)NVV * FIN;

    detect_kernel<<<1, 32>>>(vci);
    prep_w<<<2, 256>>>(W_v, W_c);
    init_mma<<<(NVV + 127) / 128, 256>>>(var_feat, W_iv, b_iv, 0, NVV);
    init_mma<<<(NVV + 127) / 128, 256>>>(con_feat, W_ic, b_ic, 2, NVV);

    int lv = 0, lc = 2;
    for (int t = 0; t < 3; t++) {
        int nlc = 5 - lc, nlv = 1 - lv;
        layer_dual<<<GRID_TC, 512, SM_DYN>>>(lv, lc, nlv, nlc,
                                             var_feat, con_feat, vci, cvi,
                                             b_v, b_c, NVV);
        lv = nlv; lc = nlc;
    }

    zero_colsum<<<1, 128>>>();
    colsum_kernel<<<(NVV + 127) / 128, 256>>>(lv, NVV);
    final_kernel<<<(NVV + 63) / 64, 256>>>(lv, W_q, b_q, Q, NVV);
}

// round 7
// speedup vs baseline: 2.7808x; 1.0362x over previous
#include <cuda_runtime.h>
#include <cuda_bf16.h>
#include <cstdint>

#define NVV 50000
#define DD 128
#define FIN 32
#define DEG 16
#define INDIM 288
#define GRID_TC 152
#define NBLK_SIDE (GRID_TC / 2)          // 76 persistent CTAs per side

#define BM32 32
#define NT32 ((NVV + BM32 - 1) / BM32)   // 1563

// W^T (k-major): 288 k-rows x 136 n-cols bf16, stride 272 B (validated R3/R5/R6)
#define WSB 272
// Act slab: 32 rows x K=288 bf16 (+pad), stride 592 B (16-aligned, phase-distinct).
#define ACT_STR 592
#define ACT_IMG (32 * ACT_STR)            // 18944
#define ACT_SLAB (2 * ACT_IMG)            // 37888 (hi | lo)

#define SM_WHI 0
#define SM_WLO 78336
#define SM_ACT 156672
#define SM_DYN (SM_ACT + 2 * ACT_SLAB)    // 232448 == opt-in max

// named barriers: 1+slot = "full", 3+slot = "empty"
#define BAR_SYNC(id)   asm volatile("bar.sync %0, 512;"   :: "r"(id) : "memory")
#define BAR_ARRIVE(id) asm volatile("bar.arrive %0, 512;" :: "r"(id) : "memory")

// ---------------------------------------------------------------------------
__device__ __align__(16) unsigned short g_wh[2][288 * 136];
__device__ __align__(16) unsigned short g_wl[2][288 * 136];
__device__ __align__(256) float g_bufs[4][(size_t)NVV * DD];
__device__ float g_colsum[DD];
__device__ int g_is64;

__device__ __forceinline__ uint32_t smem_u32(const void* p) {
    uint32_t a;
    asm("{ .reg .u64 t; cvta.to.shared.u64 t, %1; cvt.u32.u64 %0, t; }" : "=r"(a) : "l"(p));
    return a;
}
__device__ __forceinline__ void ldsm_x4(uint32_t* r, uint32_t addr) {
    asm volatile("ldmatrix.sync.aligned.m8n8.x4.shared.b16 {%0,%1,%2,%3}, [%4];"
                 : "=r"(r[0]), "=r"(r[1]), "=r"(r[2]), "=r"(r[3]) : "r"(addr));
}
__device__ __forceinline__ void ldsm_x4t(uint32_t* r, uint32_t addr) {
    asm volatile("ldmatrix.sync.aligned.m8n8.x4.trans.shared.b16 {%0,%1,%2,%3}, [%4];"
                 : "=r"(r[0]), "=r"(r[1]), "=r"(r[2]), "=r"(r[3]) : "r"(addr));
}
__device__ __forceinline__ void mma_bf16(float* d, const uint32_t* a, uint32_t b0, uint32_t b1) {
    asm volatile("mma.sync.aligned.m16n8k16.row.col.f32.bf16.bf16.f32 "
                 "{%0,%1,%2,%3}, {%4,%5,%6,%7}, {%8,%9}, {%0,%1,%2,%3};"
                 : "+f"(d[0]), "+f"(d[1]), "+f"(d[2]), "+f"(d[3])
                 : "r"(a[0]), "r"(a[1]), "r"(a[2]), "r"(a[3]), "r"(b0), "r"(b1));
}
__device__ __forceinline__ uint32_t pack_bf2(float a, float b) {
    uint32_t r;
    asm("cvt.rn.bf16x2.f32 %0, %1, %2;" : "=r"(r) : "f"(b), "f"(a));
    return r;
}
__device__ __forceinline__ void split4(float4 v, uint2& hi, uint2& lo) {
    uint32_t h01 = pack_bf2(v.x, v.y);
    uint32_t h23 = pack_bf2(v.z, v.w);
    float hx = __uint_as_float(h01 << 16);
    float hy = __uint_as_float(h01 & 0xffff0000u);
    float hz = __uint_as_float(h23 << 16);
    float hw = __uint_as_float(h23 & 0xffff0000u);
    hi.x = h01; hi.y = h23;
    lo.x = pack_bf2(v.x - hx, v.y - hy);
    lo.y = pack_bf2(v.z - hz, v.w - hw);
}

// ---------------------------------------------------------------------------
__global__ void detect_kernel(const int* __restrict__ idx32) {
    if (threadIdx.x == 0) {
        int nz = 0;
#pragma unroll
        for (int i = 0; i < 64; i++) nz |= idx32[2 * i + 1];
        g_is64 = (nz == 0) ? 1 : 0;
    }
}
__global__ void zero_colsum() { if (threadIdx.x < DD) g_colsum[threadIdx.x] = 0.f; }

__global__ void prep_w(const float* __restrict__ Wv, const float* __restrict__ Wc) {
    int which = blockIdx.x;
    const float* W = which ? Wc : Wv;
    for (int e = threadIdx.x; e < 288 * 136; e += blockDim.x) {
        int k = e / 136, nn = e - k * 136;
        float w = (nn < 128) ? W[nn * INDIM + k] : 0.f;
        uint32_t h = pack_bf2(w, 0.f);
        float hf = __uint_as_float(h << 16);
        uint32_t l = pack_bf2(w - hf, 0.f);
        g_wh[which][e] = (unsigned short)(h & 0xffff);
        g_wl[which][e] = (unsigned short)(l & 0xffff);
    }
}

// ---------------------------------------------------------------------------
// HMMA initial embedding, dual-side merged: even blocks do V, odd blocks C.
// ---------------------------------------------------------------------------
#define ISM_BH 0
#define ISM_BL 8704
#define ISM_ACT 17408
#define IACT_STR 80
#define IACT_IMG (128 * IACT_STR)       // 10240
#define NB_INIT ((NVV + 127) / 128)     // 391

__global__ __launch_bounds__(256, 1)
void init_mma(const float* __restrict__ vfeat, const float* __restrict__ cfeat,
              const float* __restrict__ Wiv, const float* __restrict__ Wic,
              const float* __restrict__ biv, const float* __restrict__ bic, int n) {
    __shared__ __align__(16) char ism[ISM_ACT + 2 * IACT_IMG];   // 37888 B
    uint32_t smb = smem_u32(ism);
    int side = blockIdx.x & 1;
    int blk = blockIdx.x >> 1;
    const float* feat = side ? cfeat : vfeat;
    const float* W    = side ? Wic : Wiv;
    const float* b    = side ? bic : biv;
    float* out = g_bufs[side ? 2 : 0];

    int tid = threadIdx.x, wid = tid >> 5, lane = tid & 31;
    int row0 = blk * 128;

    // stage W^T hi/lo (32 k x 136 n)
    for (int e = tid; e < 32 * 136; e += 256) {
        int k = e / 136, nn = e - k * 136;
        float w = (nn < 128) ? W[nn * FIN + k] : 0.f;
        uint32_t h = pack_bf2(w, 0.f);
        float hf = __uint_as_float(h << 16);
        uint32_t l = pack_bf2(w - hf, 0.f);
        *(unsigned short*)(ism + ISM_BH + k * WSB + nn * 2) = (unsigned short)(h & 0xffff);
        *(unsigned short*)(ism + ISM_BL + k * WSB + nn * 2) = (unsigned short)(l & 0xffff);
    }

    // stage feat tile: thread t -> row t/2, half t&1 (16 floats)
    {
        int r = tid >> 1, half = tid & 1;
        int gr = row0 + r;
        char* rowp = ism + ISM_ACT + r * IACT_STR + half * 32;
#pragma unroll
        for (int i = 0; i < 4; i++) {
            float4 v = (gr < n)
                ? reinterpret_cast<const float4*>(feat + (size_t)gr * FIN)[half * 4 + i]
                : make_float4(0.f, 0.f, 0.f, 0.f);
            uint2 hi, lo; split4(v, hi, lo);
            *(uint2*)(rowp + i * 8) = hi;
            *(uint2*)(rowp + IACT_IMG + i * 8) = lo;
        }
    }
    __syncthreads();

    // HMMA: 8 warps = 4(m) x 2(n); per warp 2 mt x 8 nt, K=32 (2 ksteps)
    int wm = wid >> 1, wn = wid & 1;
    int rsel = lane & 15, csel = lane >> 4;
    uint32_t aBase = smb + ISM_ACT + (uint32_t)((32 * wm + rsel) * IACT_STR + csel * 16);
    uint32_t bBase = smb + ISM_BH + (uint32_t)(rsel * WSB + csel * 16 + 128 * wn);

    float acc[2][8][4];
#pragma unroll
    for (int mt = 0; mt < 2; mt++)
#pragma unroll
        for (int nt = 0; nt < 8; nt++)
#pragma unroll
            for (int q = 0; q < 4; q++) acc[mt][nt][q] = 0.f;

#pragma unroll
    for (int ks = 0; ks < 2; ks++) {
        uint32_t ahi[2][4], alo[2][4], bhi[4][4], blo[4][4];
#pragma unroll
        for (int mt = 0; mt < 2; mt++) {
            uint32_t ra = aBase + (uint32_t)(16 * mt * IACT_STR + ks * 32);
            ldsm_x4(ahi[mt], ra);
            ldsm_x4(alo[mt], ra + IACT_IMG);
        }
#pragma unroll
        for (int np = 0; np < 4; np++) {
            uint32_t rb = bBase + (uint32_t)(ks * 16 * WSB + 32 * np);
            ldsm_x4t(bhi[np], rb);
            ldsm_x4t(blo[np], rb + (ISM_BL - ISM_BH));
        }
#pragma unroll
        for (int mt = 0; mt < 2; mt++)
#pragma unroll
            for (int nt = 0; nt < 8; nt++)
                mma_bf16(acc[mt][nt], ahi[mt], bhi[nt >> 1][2 * (nt & 1)], bhi[nt >> 1][2 * (nt & 1) + 1]);
#pragma unroll
        for (int mt = 0; mt < 2; mt++)
#pragma unroll
            for (int nt = 0; nt < 8; nt++)
                mma_bf16(acc[mt][nt], ahi[mt], blo[nt >> 1][2 * (nt & 1)], blo[nt >> 1][2 * (nt & 1) + 1]);
#pragma unroll
        for (int mt = 0; mt < 2; mt++)
#pragma unroll
            for (int nt = 0; nt < 8; nt++)
                mma_bf16(acc[mt][nt], alo[mt], bhi[nt >> 1][2 * (nt & 1)], bhi[nt >> 1][2 * (nt & 1) + 1]);
    }

    // epilogue
    int r_lo = lane >> 2;
    int cpair = (lane & 3) * 2;
#pragma unroll
    for (int mt = 0; mt < 2; mt++) {
        int ra = row0 + 32 * wm + 16 * mt + r_lo;
#pragma unroll
        for (int nt = 0; nt < 8; nt++) {
            int col = 64 * wn + 8 * nt + cpair;
            float b0 = b[col], b1 = b[col + 1];
            if (ra < n) {
                float2 v = make_float2(acc[mt][nt][0] + b0, acc[mt][nt][1] + b1);
                *(float2*)(out + (size_t)ra * DD + col) = v;
            }
            if (ra + 8 < n) {
                float2 v = make_float2(acc[mt][nt][2] + b0, acc[mt][nt][3] + b1);
                *(float2*)(out + (size_t)(ra + 8) * DD + col) = v;
            }
        }
    }
}

// ---------------------------------------------------------------------------
// Dual-side warp-specialized layer. Even blocks C side, odd blocks V side.
// Producers (warps 8-15): gather + split into REGISTERS before the slot-empty
// wait, then STS only inside the critical section (hides L2 latency).
// Consumers (warps 0-7): ldmatrix + 3-term HMMA, ks loop unrolled x2.
// ---------------------------------------------------------------------------
__global__ __launch_bounds__(512, 1)
void layer_dual(int lv_sel, int lc_sel, int nlv_sel, int nlc_sel,
                const float* __restrict__ vfeat, const float* __restrict__ cfeat,
                const int* __restrict__ vci, const int* __restrict__ cvi,
                const float* __restrict__ bv, const float* __restrict__ bc, int n)
{
    extern __shared__ char sm[];
    uint32_t smb = smem_u32(sm);

    int side = blockIdx.x & 1;   // 0 = C side, 1 = V side
    int blk = blockIdx.x >> 1;   // 0..NBLK_SIDE-1

    const float* aggsrc; const float* selfp; float* out;
    const float* feat; const int* idx32; const float* b; int which;
    if (side == 0) {  // lc_new = W_c * [gather(lv, cvi), lc, cfeat] + b_c
        aggsrc = g_bufs[lv_sel]; selfp = g_bufs[lc_sel]; out = g_bufs[nlc_sel];
        feat = cfeat; idx32 = cvi; b = bc; which = 1;
    } else {          // lv_new = W_v * [gather(lc, vci), lv, vfeat] + b_v
        aggsrc = g_bufs[lc_sel]; selfp = g_bufs[lv_sel]; out = g_bufs[nlv_sel];
        feat = vfeat; idx32 = vci; b = bv; which = 0;
    }

    int tid = threadIdx.x, wid = tid >> 5, lane = tid & 31;
    int istride = g_is64 ? 2 : 1;

    // ---- stage W hi/lo (all 512 threads) ----
    {
        const uint4* sh = (const uint4*)g_wh[which];
        const uint4* sl = (const uint4*)g_wl[which];
        uint4* dh = (uint4*)(sm + SM_WHI);
        uint4* dl = (uint4*)(sm + SM_WLO);
        for (int i = tid; i < 78336 / 16; i += 512) { dh[i] = sh[i]; dl[i] = sl[i]; }
    }
    __syncthreads();

    if (wid >= 8) {
        // ================= PRODUCERS =================
        int pw = wid - 8;              // owns rows pw*4 .. pw*4+3
        int it = 0;
        for (int tile = blk; tile < NT32; tile += NBLK_SIDE, it++) {
            int slot = it & 1;
            int row0 = tile * BM32;

            // ---- gather + split into registers (outside critical section) ----
            uint2 hA[4], lA[4], hS[4], lS[4], hF[4], lF[4];
#pragma unroll
            for (int rr = 0; rr < 4; rr++) {
                int gr = row0 + pw * 4 + rr;
                bool val = gr < n;
                const int* ip = idx32 + (size_t)(val ? gr : 0) * DEG * istride;
                int srcs[DEG];
#pragma unroll
                for (int j = 0; j < DEG; j++) srcs[j] = ip[j * istride];
                float4 v = make_float4(0.f, 0.f, 0.f, 0.f);
#pragma unroll
                for (int j = 0; j < DEG; j++) {
                    float4 t = reinterpret_cast<const float4*>(
                        aggsrc + (size_t)srcs[j] * DD)[lane];
                    v.x += t.x; v.y += t.y; v.z += t.z; v.w += t.w;
                }
                if (!val) v = make_float4(0.f, 0.f, 0.f, 0.f);
                split4(v, hA[rr], lA[rr]);
                float4 sv = val
                    ? reinterpret_cast<const float4*>(selfp + (size_t)gr * DD)[lane]
                    : make_float4(0.f, 0.f, 0.f, 0.f);
                split4(sv, hS[rr], lS[rr]);
                float4 fv = (val && lane < 8)
                    ? reinterpret_cast<const float4*>(feat + (size_t)gr * FIN)[lane]
                    : make_float4(0.f, 0.f, 0.f, 0.f);
                split4(fv, hF[rr], lF[rr]);
            }

            BAR_SYNC(3 + slot);        // wait slot empty
            char* act = sm + SM_ACT + slot * ACT_SLAB;
#pragma unroll
            for (int rr = 0; rr < 4; rr++) {
                char* rowp = act + (pw * 4 + rr) * ACT_STR;
                *(uint2*)(rowp + lane * 8) = hA[rr];
                *(uint2*)(rowp + ACT_IMG + lane * 8) = lA[rr];
                *(uint2*)(rowp + 256 + lane * 8) = hS[rr];
                *(uint2*)(rowp + ACT_IMG + 256 + lane * 8) = lS[rr];
                if (lane < 8) {
                    *(uint2*)(rowp + 512 + lane * 8) = hF[rr];
                    *(uint2*)(rowp + ACT_IMG + 512 + lane * 8) = lF[rr];
                }
            }
            BAR_ARRIVE(1 + slot);      // mark slot full
        }
    } else {
        // ================= CONSUMERS =================
        int wm = wid >> 2, wn = wid & 3;
        int rsel = lane & 15, csel = lane >> 4;
        BAR_ARRIVE(3); BAR_ARRIVE(4);  // prime both slots empty

        uint32_t aOff = (uint32_t)((16 * wm + rsel) * ACT_STR + csel * 16);
        uint32_t bBase = smb + SM_WHI + (uint32_t)(rsel * WSB + csel * 16 + 64 * wn);

        int cpair = (lane & 3) * 2;
        float2 bb[4];
#pragma unroll
        for (int nt = 0; nt < 4; nt++) {
            int col = 32 * wn + 8 * nt + cpair;
            bb[nt].x = b[col]; bb[nt].y = b[col + 1];
        }

        int it = 0;
        for (int tile = blk; tile < NT32; tile += NBLK_SIDE, it++) {
            int slot = it & 1;
            BAR_SYNC(1 + slot);        // wait slot full
            uint32_t aBase = smb + SM_ACT + (uint32_t)(slot * ACT_SLAB) + aOff;

            float acc[4][4];
#pragma unroll
            for (int nt = 0; nt < 4; nt++)
#pragma unroll
                for (int q = 0; q < 4; q++) acc[nt][q] = 0.f;

#pragma unroll 2
            for (int ks = 0; ks < 18; ks++) {
                uint32_t ahi[4], alo[4], bhi[2][4], blo[2][4];
                uint32_t ra = aBase + (uint32_t)(ks * 32);
                ldsm_x4(ahi, ra);
                ldsm_x4(alo, ra + ACT_IMG);
#pragma unroll
                for (int np = 0; np < 2; np++) {
                    uint32_t rb = bBase + (uint32_t)(ks * 16 * WSB + 32 * np);
                    ldsm_x4t(bhi[np], rb);
                    ldsm_x4t(blo[np], rb + (SM_WLO - SM_WHI));
                }
#pragma unroll
                for (int nt = 0; nt < 4; nt++)
                    mma_bf16(acc[nt], ahi, bhi[nt >> 1][2 * (nt & 1)], bhi[nt >> 1][2 * (nt & 1) + 1]);
#pragma unroll
                for (int nt = 0; nt < 4; nt++)
                    mma_bf16(acc[nt], ahi, blo[nt >> 1][2 * (nt & 1)], blo[nt >> 1][2 * (nt & 1) + 1]);
#pragma unroll
                for (int nt = 0; nt < 4; nt++)
                    mma_bf16(acc[nt], alo, bhi[nt >> 1][2 * (nt & 1)], bhi[nt >> 1][2 * (nt & 1) + 1]);
            }
            BAR_ARRIVE(3 + slot);      // slot free (acc in regs)

            // epilogue
            int row0 = tile * BM32;
            int r_lo = lane >> 2;
            int ra0 = row0 + 16 * wm + r_lo;
#pragma unroll
            for (int nt = 0; nt < 4; nt++) {
                int col = 32 * wn + 8 * nt + cpair;
                if (ra0 < n) {
                    float2 v = make_float2(acc[nt][0] + bb[nt].x, acc[nt][1] + bb[nt].y);
                    *(float2*)(out + (size_t)ra0 * DD + col) = v;
                }
                if (ra0 + 8 < n) {
                    float2 v = make_float2(acc[nt][2] + bb[nt].x, acc[nt][3] + bb[nt].y);
                    *(float2*)(out + (size_t)(ra0 + 8) * DD + col) = v;
                }
            }
        }
    }
}

// ---------------------------------------------------------------------------
__global__ void colsum_kernel(int lv_sel, int n) {
    const float* lv = g_bufs[lv_sel];
    __shared__ float s[DD];
    int tid = threadIdx.x;
    int col = tid & (DD - 1);
    int half = tid >> 7;
    int r0 = blockIdx.x * 128 + half * 64;
    int r1 = r0 + 64; if (r1 > n) r1 = n;
    float acc = 0.f;
    for (int r = r0; r < r1; r++) acc += lv[(size_t)r * DD + col];
    if (half) s[col] = acc;
    __syncthreads();
    if (!half) atomicAdd(&g_colsum[col], acc + s[col]);
}

__global__ void final_kernel(int lv_sel, const float* __restrict__ Wq,
                             const float* __restrict__ bq,
                             float* __restrict__ Q, int n) {
    const float* lv = g_bufs[lv_sel];
    __shared__ float sW[DD];
    __shared__ float s_s;
    int tid = threadIdx.x;
    if (tid < DD) sW[tid] = Wq[DD + tid];
    if (tid < 32) {
        float p = 0.f;
#pragma unroll
        for (int t = 0; t < 4; t++) p += g_colsum[tid + 32 * t] * Wq[tid + 32 * t];
#pragma unroll
        for (int o = 16; o > 0; o >>= 1) p += __shfl_xor_sync(0xffffffffu, p, o);
        if (tid == 0) s_s = p + bq[0];
    }
    __syncthreads();
    int warp = tid >> 5, lane = tid & 31;
    int base = blockIdx.x * 64 + warp * 8;
    for (int i = 0; i < 8; i++) {
        int row = base + i;
        if (row >= n) break;
        const float* rp = lv + (size_t)row * DD;
        float p = rp[lane]      * sW[lane]
                + rp[lane + 32] * sW[lane + 32]
                + rp[lane + 64] * sW[lane + 64]
                + rp[lane + 96] * sW[lane + 96];
#pragma unroll
        for (int o = 16; o > 0; o >>= 1) p += __shfl_xor_sync(0xffffffffu, p, o);
        if (lane == 0) Q[row] = s_s + p;
    }
}

// ---------------------------------------------------------------------------
extern "C" void kernel_launch(void* const* d_in, const int* in_sizes, int n_in,
                              void* d_out, int out_size) {
    const float* x    = (const float*)d_in[0];
    const int*   vci  = (const int*)d_in[1];
    const int*   cvi  = (const int*)d_in[2];
    const float* W_iv = (const float*)d_in[3];
    const float* b_iv = (const float*)d_in[4];
    const float* W_ic = (const float*)d_in[5];
    const float* b_ic = (const float*)d_in[6];
    const float* W_v  = (const float*)d_in[7];
    const float* b_v  = (const float*)d_in[8];
    const float* W_c  = (const float*)d_in[9];
    const float* b_c  = (const float*)d_in[10];
    const float* W_q  = (const float*)d_in[11];
    const float* b_q  = (const float*)d_in[12];
    float* Q = (float*)d_out;

    cudaFuncSetAttribute(layer_dual,
                         cudaFuncAttributeMaxDynamicSharedMemorySize, SM_DYN);

    const float* var_feat = x;
    const float* con_feat = x + (size_t)NVV * FIN;

    detect_kernel<<<1, 32>>>(vci);
    prep_w<<<2, 256>>>(W_v, W_c);
    init_mma<<<2 * NB_INIT, 256>>>(var_feat, con_feat, W_iv, W_ic, b_iv, b_ic, NVV);

    int lv = 0, lc = 2;
    for (int t = 0; t < 3; t++) {
        int nlc = 5 - lc, nlv = 1 - lv;
        layer_dual<<<GRID_TC, 512, SM_DYN>>>(lv, lc, nlv, nlc,
                                             var_feat, con_feat, vci, cvi,
                                             b_v, b_c, NVV);
        lv = nlv; lc = nlc;
    }

    zero_colsum<<<1, 128>>>();
    colsum_kernel<<<(NVV + 127) / 128, 256>>>(lv, NVV);
    final_kernel<<<(NVV + 63) / 64, 256>>>(lv, W_q, b_q, Q, NVV);
}